// round 1
// baseline (speedup 1.0000x reference)
#include <cuda_runtime.h>
#include <cuda_bf16.h>
#include <cstddef>

#define NPROJ 180
#define DH    192
#define DW    384
#define NX    96
#define NY    96
#define NZ    96

__global__ __launch_bounds__(NX)
void cone_bp_kernel(const float* __restrict__ sino,   // [B, P, H, W]
                    const float* __restrict__ mats,   // [P, 3, 4]
                    float* __restrict__ out)          // [B, Z, Y, X]
{
    // Per-projection coefficients: uvw = A * x + C, where A depends only on P,
    // C depends on (y, z) of this block.
    __shared__ float4 sA[NPROJ];   // (a_u, a_v, a_w, c_u)
    __shared__ float2 sC[NPROJ];   // (c_v, c_w)

    const int y = blockIdx.x;
    const int z = blockIdx.y;
    const int b = blockIdx.z;
    const int tx = threadIdx.x;

    const float yw = (float)y - 47.5f;
    const float zw = (float)z - 47.5f;

    for (int p = tx; p < NPROJ; p += NX) {
        const float* P = mats + p * 12;
        float a0 = P[0], a1 = P[4], a2 = P[8];
        float c0 = fmaf(P[1],  yw, fmaf(P[2],  zw, P[3]));
        float c1 = fmaf(P[5],  yw, fmaf(P[6],  zw, P[7]));
        float c2 = fmaf(P[9],  yw, fmaf(P[10], zw, P[11]));
        sA[p] = make_float4(a0, a1, a2, c0);
        sC[p] = make_float2(c1, c2);
    }
    __syncthreads();

    const float xw = (float)tx - 47.5f;
    const float* img = sino + (size_t)b * (NPROJ * DH * DW);

    float acc = 0.0f;

    #pragma unroll 4
    for (int p = 0; p < NPROJ; ++p) {
        float4 A = sA[p];
        float2 C = sC[p];
        float uw = fmaf(A.x, xw, A.w);
        float vw = fmaf(A.y, xw, C.x);
        float w  = fmaf(A.z, xw, C.y);

        float rw;
        asm("rcp.approx.f32 %0, %1;" : "=f"(rw) : "f"(w));

        float u   = uw * rw;
        float v   = vw * rw;
        float iw2 = rw * rw;

        float uf = floorf(u), vf = floorf(v);
        int   ui = (int)uf,   vi = (int)vf;
        float fu = u - uf,    fv = v - vf;

        // Geometry guarantees all 4 taps are strictly inside the detector:
        // |u - cu| <= ~118 < 191.5, |v - cv| <= ~84 < 95.5 -> no bounds checks.
        const float* q = img + (size_t)p * (DH * DW) + vi * DW + ui;
        float t00 = __ldg(q);
        float t01 = __ldg(q + 1);
        float t10 = __ldg(q + DW);
        float t11 = __ldg(q + DW + 1);

        float top = fmaf(fu, t01 - t00, t00);
        float bot = fmaf(fu, t11 - t10, t10);
        float val = fmaf(fv, bot - top, top);

        acc = fmaf(val, iw2, acc);
    }

    out[(((size_t)b * NZ + z) * NY + y) * NX + tx] = acc;
}

extern "C" void kernel_launch(void* const* d_in, const int* in_sizes, int n_in,
                              void* d_out, int out_size)
{
    // Identify inputs by size (x is huge, proj_matrices is 180*12 = 2160 floats).
    const float* sino = (const float*)d_in[0];
    const float* mats = (const float*)d_in[1];
    if (n_in >= 2 && in_sizes[0] == NPROJ * 12) {
        sino = (const float*)d_in[1];
        mats = (const float*)d_in[0];
    }
    float* out = (float*)d_out;

    dim3 grid(NY, NZ, 2);
    dim3 block(NX);
    cone_bp_kernel<<<grid, block>>>(sino, mats, out);
}